// round 8
// baseline (speedup 1.0000x reference)
#include <cuda_runtime.h>
#include <cstdint>

// TopK keep: zero all but the K=512 largest entries per 4096-wide row.
// One CTA (256 thr) per row, 16 floats/thread register-resident.
//
// Pipeline: (1) 64-bin offset histogram of candidates (x >= 0.875, raw-bit
// binning valid since candidates are positive) -> warp-0 suffix scan finds
// winning bin + in-bin rank; (2) warp-aggregated compaction of the winning
// bin's values (~90) into smem; (3) warp-0 20-bit binary search over
// register-cached values gives exact K-th key T, need, n_eq; (4) emit.
// Exactness guards: clamp-bin / tot<K -> full binary-search fallback;
// m>256 -> smem-loop search; need!=n_eq -> stable lowest-index tie ranking.

#define D_DIM   4096
#define K_KEEP  512
#define NT      256
#define PT      16
#define NW      8
#define T0F     0.875f
#define B1OFF   0x3F6u        // (f2u(0.875) >> 20)

__device__ __forceinline__ unsigned f2k(float f) {
    unsigned u = __float_as_uint(f);
    return u ^ ((unsigned)((int)u >> 31) | 0x80000000u);
}
__device__ __forceinline__ float k2f(unsigned k) {
    return __uint_as_float(k ^ ((unsigned)((int)(~k) >> 31) | 0x80000000u));
}

__global__ __launch_bounds__(NT, 6)
void topk_keep_kernel(const float* __restrict__ x, float* __restrict__ out)
{
    __shared__ unsigned hist[64];
    __shared__ __align__(16) unsigned buf[4096];   // winning-bin values (worst case: whole row)
    __shared__ unsigned cnt, selb, selk, stot, sT, sneed, sneq;
    __shared__ unsigned wsum[NW];

    const int tid  = threadIdx.x;
    const int lane = tid & 31;
    const int warp = tid >> 5;
    const size_t row = (size_t)blockIdx.x * D_DIM;

    // ---- load: 16 floats in registers ----
    const float4* xr = reinterpret_cast<const float4*>(x + row) + tid * 4;
    float f0[PT];
    {
        float4 v0 = xr[0], v1 = xr[1], v2 = xr[2], v3 = xr[3];
        f0[0]=v0.x;  f0[1]=v0.y;  f0[2]=v0.z;  f0[3]=v0.w;
        f0[4]=v1.x;  f0[5]=v1.y;  f0[6]=v1.z;  f0[7]=v1.w;
        f0[8]=v2.x;  f0[9]=v2.y;  f0[10]=v2.z; f0[11]=v2.w;
        f0[12]=v3.x; f0[13]=v3.y; f0[14]=v3.z; f0[15]=v3.w;
    }

    if (tid < 64) hist[tid] = 0u;
    if (tid == 0) cnt = 0u;
    __syncthreads();                                           // S1

    // ---- L1: 64 offset bins, candidates only ----
#pragma unroll
    for (int i = 0; i < PT; ++i) {
        if (f0[i] >= T0F) {
            unsigned b = (__float_as_uint(f0[i]) >> 20) - B1OFF;
            atomicAdd(&hist[umin(b, 63u)], 1u);
        }
    }
    __syncthreads();                                           // S2

    // ---- warp-0 scan of 64 bins: winning bin + in-bin rank ----
    if (warp == 0) {
        unsigned c_lo = hist[lane];         // bins 0..31
        unsigned c_hi = hist[32 + lane];    // bins 32..63
        unsigned shi = c_hi, slo = c_lo;    // inclusive suffix sums across lanes
#pragma unroll
        for (int o = 1; o < 32; o <<= 1) {
            unsigned t1 = __shfl_down_sync(0xffffffffu, shi, o);
            unsigned t2 = __shfl_down_sync(0xffffffffu, slo, o);
            if (lane + o < 32) { shi += t1; slo += t2; }
        }
        unsigned totHi = __shfl_sync(0xffffffffu, shi, 0);
        slo += totHi;                       // suffix including all hi bins
        unsigned tot = __shfl_sync(0xffffffffu, slo, 0);
        if (lane == 0) stot = tot;
        if (tot >= K_KEEP) {
            if (shi >= K_KEEP && shi - c_hi < K_KEEP) {
                selb = 32u + (unsigned)lane; selk = K_KEEP - (shi - c_hi);
            }
            if (slo >= K_KEEP && slo - c_lo < K_KEEP) {
                selb = (unsigned)lane;       selk = K_KEEP - (slo - c_lo);
            }
        }
    }
    __syncthreads();                                           // S3

    const unsigned tot = stot;
    const unsigned b1s = selb;

    if (tot < K_KEEP || b1s == 63u) {
        // ---- exact fallback: 32-step binary search in key space ----
        unsigned k0[PT];
#pragma unroll
        for (int i = 0; i < PT; ++i) k0[i] = f2k(f0[i]);
        unsigned lo = 0u, hi = 0xFFFFFFFFu;
#pragma unroll 1
        while (lo < hi) {
            unsigned mid = lo + ((hi - lo) >> 1) + ((hi - lo) & 1u);
            unsigned c = 0;
#pragma unroll
            for (int i = 0; i < PT; ++i) c += (k0[i] >= mid) ? 1u : 0u;
            c = __reduce_add_sync(0xffffffffu, c);
            if (lane == 0) wsum[warp] = c;
            __syncthreads();
            if (warp == 0) {
                unsigned v = (lane < NW) ? wsum[lane] : 0u;
#pragma unroll
                for (int o = 4; o > 0; o >>= 1) v += __shfl_down_sync(0xffffffffu, v, o);
                if (lane == 0) stot = v;
            }
            __syncthreads();
            if (stot >= K_KEEP) lo = mid; else hi = mid - 1u;
        }
        const unsigned T = lo;
        unsigned cg = 0, ceq = 0;
#pragma unroll
        for (int i = 0; i < PT; ++i) {
            cg  += (k0[i] > T)  ? 1u : 0u;
            ceq += (k0[i] == T) ? 1u : 0u;
        }
        {
            unsigned c = __reduce_add_sync(0xffffffffu, cg);
            if (lane == 0) wsum[warp] = c;
            __syncthreads();
            if (warp == 0) {
                unsigned v = (lane < NW) ? wsum[lane] : 0u;
#pragma unroll
                for (int o = 4; o > 0; o >>= 1) v += __shfl_down_sync(0xffffffffu, v, o);
                if (lane == 0) stot = v;
            }
            __syncthreads();
        }
        const unsigned need = K_KEEP - stot;
        __syncthreads();
        unsigned p = ceq;
#pragma unroll
        for (int o = 1; o < 32; o <<= 1) {
            unsigned v = __shfl_up_sync(0xffffffffu, p, o);
            if (lane >= o) p += v;
        }
        if (lane == 31) wsum[warp] = p;
        __syncthreads();
        unsigned woff = 0;
#pragma unroll
        for (int w = 0; w < NW; ++w) if (w < warp) woff += wsum[w];
        unsigned rank = woff + p - ceq;
        float4* outr = reinterpret_cast<float4*>(out + row) + tid * 4;
#pragma unroll
        for (int j = 0; j < 4; ++j) {
            float r[4];
#pragma unroll
            for (int c2 = 0; c2 < 4; ++c2) {
                unsigned k = k0[j * 4 + c2];
                bool eq = (k == T);
                bool keep = (k > T) || (eq && (rank < need));
                r[c2] = keep ? k2f(k) : 0.0f;
                rank += eq ? 1u : 0u;
            }
            outr[j] = make_float4(r[0], r[1], r[2], r[3]);
        }
        return;
    }

    // ---- compact winning-bin values into buf (warp-aggregated append) ----
    const unsigned b1full = B1OFF + b1s;
#pragma unroll
    for (int i = 0; i < PT; ++i) {
        unsigned u = __float_as_uint(f0[i]);
        bool pred = (f0[i] >= T0F) && ((u >> 20) == b1full);
        unsigned m = __ballot_sync(0xffffffffu, pred);
        if (pred) {
            int leader = __ffs(m) - 1;
            unsigned base = 0;
            if (lane == leader) base = atomicAdd(&cnt, (unsigned)__popc(m));
            base = __shfl_sync(m, base, leader);
            buf[base + __popc(m & ((1u << lane) - 1u))] = u;
        }
    }
    __syncthreads();                                           // S4

    // ---- warp-0 exact select among buf values (20-bit binary search) ----
    if (warp == 0) {
        const unsigned m   = cnt;
        const unsigned kth = selk;
        unsigned lo = b1full << 20, hi = (b1full << 20) | 0xFFFFFu;
        if (m <= 256u) {
            unsigned vv[8];
#pragma unroll
            for (int t = 0; t < 8; ++t) {
                unsigned j = (unsigned)lane + t * 32u;
                vv[t] = (j < m) ? buf[j] : 0u;   // sentinel 0 < lo, never counted
            }
#pragma unroll 1
            while (lo < hi) {
                unsigned mid = lo + ((hi - lo) >> 1) + ((hi - lo) & 1u);
                unsigned c = 0;
#pragma unroll
                for (int t = 0; t < 8; ++t) c += (vv[t] >= mid) ? 1u : 0u;
                c = __reduce_add_sync(0xffffffffu, c);
                if (c >= kth) lo = mid; else hi = mid - 1u;
            }
            unsigned cg = 0, ce = 0;
#pragma unroll
            for (int t = 0; t < 8; ++t) {
                cg += (vv[t] > lo)  ? 1u : 0u;
                ce += (vv[t] == lo) ? 1u : 0u;
            }
            cg = __reduce_add_sync(0xffffffffu, cg);
            ce = __reduce_add_sync(0xffffffffu, ce);
            if (lane == 0) { sT = lo; sneed = kth - cg; sneq = ce; }
        } else {
            // rare: large tie-cluster bin — exact smem-loop search
#pragma unroll 1
            while (lo < hi) {
                unsigned mid = lo + ((hi - lo) >> 1) + ((hi - lo) & 1u);
                unsigned c = 0;
                for (unsigned j = lane; j < m; j += 32u) c += (buf[j] >= mid) ? 1u : 0u;
                c = __reduce_add_sync(0xffffffffu, c);
                if (c >= kth) lo = mid; else hi = mid - 1u;
            }
            unsigned cg = 0, ce = 0;
            for (unsigned j = lane; j < m; j += 32u) {
                unsigned v = buf[j];
                cg += (v > lo)  ? 1u : 0u;
                ce += (v == lo) ? 1u : 0u;
            }
            cg = __reduce_add_sync(0xffffffffu, cg);
            ce = __reduce_add_sync(0xffffffffu, ce);
            if (lane == 0) { sT = lo; sneed = kth - cg; sneq = ce; }
        }
    }
    __syncthreads();                                           // S5

    const unsigned T    = sT;
    const unsigned need = sneed;
    const unsigned neq  = sneq;
    const float    Tf   = __uint_as_float(T);   // positive float

    if (need == neq) {
        // ---- fast emit: keep everything >= Tf ----
        float4* outr = reinterpret_cast<float4*>(out + row) + tid * 4;
#pragma unroll
        for (int j = 0; j < 4; ++j) {
            float4 o;
            o.x = (f0[j*4+0] >= Tf) ? f0[j*4+0] : 0.0f;
            o.y = (f0[j*4+1] >= Tf) ? f0[j*4+1] : 0.0f;
            o.z = (f0[j*4+2] >= Tf) ? f0[j*4+2] : 0.0f;
            o.w = (f0[j*4+3] >= Tf) ? f0[j*4+3] : 0.0f;
            outr[j] = o;
        }
        return;
    }

    // ---- rare tie path: stable rank, lowest index first ----
    unsigned ceq = 0;
#pragma unroll
    for (int i = 0; i < PT; ++i) ceq += (f0[i] == Tf) ? 1u : 0u;
    unsigned p = ceq;
#pragma unroll
    for (int o = 1; o < 32; o <<= 1) {
        unsigned v = __shfl_up_sync(0xffffffffu, p, o);
        if (lane >= o) p += v;
    }
    if (lane == 31) wsum[warp] = p;
    __syncthreads();
    unsigned woff = 0;
#pragma unroll
    for (int w = 0; w < NW; ++w) if (w < warp) woff += wsum[w];
    unsigned rank = woff + p - ceq;

    float4* outr = reinterpret_cast<float4*>(out + row) + tid * 4;
#pragma unroll
    for (int j = 0; j < 4; ++j) {
        float r[4];
#pragma unroll
        for (int c = 0; c < 4; ++c) {
            float f = f0[j * 4 + c];
            bool eq = (f == Tf);
            bool keep = (f > Tf) || (eq && (rank < need));
            r[c] = keep ? f : 0.0f;
            rank += eq ? 1u : 0u;
        }
        outr[j] = make_float4(r[0], r[1], r[2], r[3]);
    }
}

extern "C" void kernel_launch(void* const* d_in, const int* in_sizes, int n_in,
                              void* d_out, int out_size) {
    const float* x = (const float*)d_in[0];
    float* out = (float*)d_out;
    int rows = out_size / D_DIM;   // 16384
    topk_keep_kernel<<<rows, NT>>>(x, out);
}

// round 9
// speedup vs baseline: 1.4673x; 1.4673x over previous
#include <cuda_runtime.h>
#include <cstdint>

// TopK keep: zero all but the K=512 largest entries per 4096-wide row.
// One CTA (256 thr) per row, 16 floats/thread register-resident.
//
// Single fine radix level: 1024 bins of (u>>14) - 0xFD80 exactly tile
// [0.875, 3.496) for positive floats (raw-bit order == float order).
// Parallel 256-thread suffix scan -> winning bin (m ~ 1-4 values) + rank.
// Ballot-compact the bin, warp-0 bitonic sort resolves exact K-th key T.
// Guards for exactness on any input: tot<K or clamp-bin -> full binary
// search fallback; m>32 -> register binary search; m>256 -> smem loop;
// need != n_eq -> stable lowest-index tie ranking.

#define D_DIM   4096
#define K_KEEP  512
#define NT      256
#define PT      16
#define NW      8
#define T0F     0.875f
#define BOFF    0xFD80u      // f2u(0.875) >> 14

__device__ __forceinline__ unsigned f2k(float f) {
    unsigned u = __float_as_uint(f);
    return u ^ ((unsigned)((int)u >> 31) | 0x80000000u);
}
__device__ __forceinline__ float k2f(unsigned k) {
    return __uint_as_float(k ^ ((unsigned)((int)(~k) >> 31) | 0x80000000u));
}

__global__ __launch_bounds__(NT, 6)
void topk_keep_kernel(const float* __restrict__ x, float* __restrict__ out)
{
    __shared__ __align__(16) unsigned hist[1024];   // 4KB
    __shared__ __align__(16) unsigned buf[4096];    // winning-bin values (worst case)
    __shared__ unsigned wsum[NW];
    __shared__ unsigned cnt, selb, selk, stot, sT, sneed, sneq;

    const int tid  = threadIdx.x;
    const int lane = tid & 31;
    const int warp = tid >> 5;
    const size_t row = (size_t)blockIdx.x * D_DIM;

    // ---- load: 16 floats in registers ----
    const float4* xr = reinterpret_cast<const float4*>(x + row) + tid * 4;
    float f0[PT];
    {
        float4 v0 = xr[0], v1 = xr[1], v2 = xr[2], v3 = xr[3];
        f0[0]=v0.x;  f0[1]=v0.y;  f0[2]=v0.z;  f0[3]=v0.w;
        f0[4]=v1.x;  f0[5]=v1.y;  f0[6]=v1.z;  f0[7]=v1.w;
        f0[8]=v2.x;  f0[9]=v2.y;  f0[10]=v2.z; f0[11]=v2.w;
        f0[12]=v3.x; f0[13]=v3.y; f0[14]=v3.z; f0[15]=v3.w;
    }

    reinterpret_cast<uint4*>(hist)[tid] = make_uint4(0u,0u,0u,0u);
    if (tid == 0) cnt = 0u;
    __syncthreads();                                           // S1

    // ---- fine histogram: 1024 bins, candidates only ----
#pragma unroll
    for (int i = 0; i < PT; ++i) {
        if (f0[i] >= T0F) {
            unsigned b = (__float_as_uint(f0[i]) >> 14) - BOFF;
            atomicAdd(&hist[umin(b, 1023u)], 1u);
        }
    }
    __syncthreads();                                           // S2

    // ---- parallel suffix scan over 1024 bins (4 bins/thread) ----
    unsigned kth = K_KEEP;
    unsigned tot;
    {
        uint4 a = reinterpret_cast<const uint4*>(hist)[tid];
        unsigned ct = a.x + a.y + a.z + a.w;
        unsigned s = ct;
#pragma unroll
        for (int o = 1; o < 32; o <<= 1) {
            unsigned v = __shfl_down_sync(0xffffffffu, s, o);
            if (lane + o < 32) s += v;
        }
        if (lane == 0) wsum[warp] = s;
        __syncthreads();                                       // S3
        unsigned addh = 0; tot = 0;
#pragma unroll
        for (int w = 0; w < NW; ++w) {
            unsigned v = wsum[w];
            tot += v;
            if (w > warp) addh += v;
        }
        if (tot >= K_KEEP) {
            unsigned beyond = (s - ct) + addh;   // count in bins above my 4
            if (beyond < kth && beyond + ct >= kth) {
                unsigned carr[4] = {a.x, a.y, a.z, a.w};
                unsigned rb = beyond;
#pragma unroll
                for (int j = 3; j >= 0; --j) {
                    unsigned c = carr[j];
                    if (rb < kth && rb + c >= kth) { selb = (unsigned)(tid * 4 + j); selk = kth - rb; }
                    rb += c;
                }
            }
        }
        __syncthreads();                                       // S4
    }

    const unsigned b1s = selb;

    if (tot < K_KEEP || b1s == 1023u) {
        // ---- exact fallback: 32-step binary search in key space ----
        unsigned k0[PT];
#pragma unroll
        for (int i = 0; i < PT; ++i) k0[i] = f2k(f0[i]);
        unsigned lo = 0u, hi = 0xFFFFFFFFu;
#pragma unroll 1
        while (lo < hi) {
            unsigned mid = lo + ((hi - lo) >> 1) + ((hi - lo) & 1u);
            unsigned c = 0;
#pragma unroll
            for (int i = 0; i < PT; ++i) c += (k0[i] >= mid) ? 1u : 0u;
            c = __reduce_add_sync(0xffffffffu, c);
            if (lane == 0) wsum[warp] = c;
            __syncthreads();
            if (warp == 0) {
                unsigned v = (lane < NW) ? wsum[lane] : 0u;
#pragma unroll
                for (int o = 4; o > 0; o >>= 1) v += __shfl_down_sync(0xffffffffu, v, o);
                if (lane == 0) stot = v;
            }
            __syncthreads();
            if (stot >= K_KEEP) lo = mid; else hi = mid - 1u;
        }
        const unsigned T = lo;
        unsigned cg = 0, ceq = 0;
#pragma unroll
        for (int i = 0; i < PT; ++i) {
            cg  += (k0[i] > T)  ? 1u : 0u;
            ceq += (k0[i] == T) ? 1u : 0u;
        }
        {
            unsigned c = __reduce_add_sync(0xffffffffu, cg);
            if (lane == 0) wsum[warp] = c;
            __syncthreads();
            if (warp == 0) {
                unsigned v = (lane < NW) ? wsum[lane] : 0u;
#pragma unroll
                for (int o = 4; o > 0; o >>= 1) v += __shfl_down_sync(0xffffffffu, v, o);
                if (lane == 0) stot = v;
            }
            __syncthreads();
        }
        const unsigned need = K_KEEP - stot;
        __syncthreads();
        unsigned p = ceq;
#pragma unroll
        for (int o = 1; o < 32; o <<= 1) {
            unsigned v = __shfl_up_sync(0xffffffffu, p, o);
            if (lane >= o) p += v;
        }
        if (lane == 31) wsum[warp] = p;
        __syncthreads();
        unsigned woff = 0;
#pragma unroll
        for (int w = 0; w < NW; ++w) if (w < warp) woff += wsum[w];
        unsigned rank = woff + p - ceq;
        float4* outr = reinterpret_cast<float4*>(out + row) + tid * 4;
#pragma unroll
        for (int j = 0; j < 4; ++j) {
            float r[4];
#pragma unroll
            for (int c2 = 0; c2 < 4; ++c2) {
                unsigned k = k0[j * 4 + c2];
                bool eq = (k == T);
                bool keep = (k > T) || (eq && (rank < need));
                r[c2] = keep ? k2f(k) : 0.0f;
                rank += eq ? 1u : 0u;
            }
            outr[j] = make_float4(r[0], r[1], r[2], r[3]);
        }
        return;
    }

    // ---- compact winning-bin values (warp-aggregated append) ----
    const unsigned binKey = BOFF + b1s;   // u>>14 of winning bin, b1s < 1023
#pragma unroll
    for (int i = 0; i < PT; ++i) {
        unsigned u = __float_as_uint(f0[i]);
        bool pred = ((u >> 14) == binKey);
        unsigned m = __ballot_sync(0xffffffffu, pred);
        if (pred) {
            int leader = __ffs(m) - 1;
            unsigned base = 0;
            if (lane == leader) base = atomicAdd(&cnt, (unsigned)__popc(m));
            base = __shfl_sync(m, base, leader);
            buf[base + __popc(m & ((1u << lane) - 1u))] = u;
        }
    }
    __syncthreads();                                           // S5

    // ---- warp-0 exact select within bin ----
    if (warp == 0) {
        const unsigned m   = cnt;
        const unsigned kk  = selk;    // 1..m
        if (m <= 32u) {
            // bitonic sort ascending; sentinels (0) sink to low lanes
            unsigned orig = (lane < (int)m) ? buf[lane] : 0u;
            unsigned v = orig;
#pragma unroll
            for (int k = 2; k <= 32; k <<= 1) {
#pragma unroll
                for (int j = k >> 1; j > 0; j >>= 1) {
                    unsigned o = __shfl_xor_sync(0xffffffffu, v, j);
                    bool dirUp   = ((lane & k) == 0);
                    bool takeMax = ((lane & j) != 0);
                    unsigned mn = umin(v, o), mx = umax(v, o);
                    v = (dirUp == takeMax) ? mx : mn;
                }
            }
            unsigned T = __shfl_sync(0xffffffffu, v, 32 - (int)kk);
            unsigned cg = __reduce_add_sync(0xffffffffu, (orig > T)  ? 1u : 0u);
            unsigned ce = __reduce_add_sync(0xffffffffu, (orig == T) ? 1u : 0u);
            if (lane == 0) { sT = T; sneed = kk - cg; sneq = ce; }
        } else {
            unsigned lo = binKey << 14, hi = (binKey << 14) | 0x3FFFu;
            if (m <= 256u) {
                unsigned vv[8];
#pragma unroll
                for (int t = 0; t < 8; ++t) {
                    unsigned j = (unsigned)lane + t * 32u;
                    vv[t] = (j < m) ? buf[j] : 0u;
                }
#pragma unroll 1
                while (lo < hi) {
                    unsigned mid = lo + ((hi - lo) >> 1) + ((hi - lo) & 1u);
                    unsigned c = 0;
#pragma unroll
                    for (int t = 0; t < 8; ++t) c += (vv[t] >= mid) ? 1u : 0u;
                    c = __reduce_add_sync(0xffffffffu, c);
                    if (c >= kk) lo = mid; else hi = mid - 1u;
                }
                unsigned cg = 0, ce = 0;
#pragma unroll
                for (int t = 0; t < 8; ++t) {
                    cg += (vv[t] > lo)  ? 1u : 0u;
                    ce += (vv[t] == lo) ? 1u : 0u;
                }
                cg = __reduce_add_sync(0xffffffffu, cg);
                ce = __reduce_add_sync(0xffffffffu, ce);
                if (lane == 0) { sT = lo; sneed = kk - cg; sneq = ce; }
            } else {
#pragma unroll 1
                while (lo < hi) {
                    unsigned mid = lo + ((hi - lo) >> 1) + ((hi - lo) & 1u);
                    unsigned c = 0;
                    for (unsigned j = lane; j < m; j += 32u) c += (buf[j] >= mid) ? 1u : 0u;
                    c = __reduce_add_sync(0xffffffffu, c);
                    if (c >= kk) lo = mid; else hi = mid - 1u;
                }
                unsigned cg = 0, ce = 0;
                for (unsigned j = lane; j < m; j += 32u) {
                    unsigned v = buf[j];
                    cg += (v > lo)  ? 1u : 0u;
                    ce += (v == lo) ? 1u : 0u;
                }
                cg = __reduce_add_sync(0xffffffffu, cg);
                ce = __reduce_add_sync(0xffffffffu, ce);
                if (lane == 0) { sT = lo; sneed = kk - cg; sneq = ce; }
            }
        }
    }
    __syncthreads();                                           // S6

    const unsigned need = sneed;
    const unsigned neq  = sneq;
    const float    Tf   = __uint_as_float(sT);   // positive float

    if (need == neq) {
        // ---- fast emit: keep everything >= Tf ----
        float4* outr = reinterpret_cast<float4*>(out + row) + tid * 4;
#pragma unroll
        for (int j = 0; j < 4; ++j) {
            float4 o;
            o.x = (f0[j*4+0] >= Tf) ? f0[j*4+0] : 0.0f;
            o.y = (f0[j*4+1] >= Tf) ? f0[j*4+1] : 0.0f;
            o.z = (f0[j*4+2] >= Tf) ? f0[j*4+2] : 0.0f;
            o.w = (f0[j*4+3] >= Tf) ? f0[j*4+3] : 0.0f;
            outr[j] = o;
        }
        return;
    }

    // ---- rare tie path: stable rank, lowest index first ----
    unsigned ceq = 0;
#pragma unroll
    for (int i = 0; i < PT; ++i) ceq += (f0[i] == Tf) ? 1u : 0u;
    unsigned p = ceq;
#pragma unroll
    for (int o = 1; o < 32; o <<= 1) {
        unsigned v = __shfl_up_sync(0xffffffffu, p, o);
        if (lane >= o) p += v;
    }
    if (lane == 31) wsum[warp] = p;
    __syncthreads();
    unsigned woff = 0;
#pragma unroll
    for (int w = 0; w < NW; ++w) if (w < warp) woff += wsum[w];
    unsigned rank = woff + p - ceq;

    float4* outr = reinterpret_cast<float4*>(out + row) + tid * 4;
#pragma unroll
    for (int j = 0; j < 4; ++j) {
        float r[4];
#pragma unroll
        for (int c = 0; c < 4; ++c) {
            float f = f0[j * 4 + c];
            bool eq = (f == Tf);
            bool keep = (f > Tf) || (eq && (rank < need));
            r[c] = keep ? f : 0.0f;
            rank += eq ? 1u : 0u;
        }
        outr[j] = make_float4(r[0], r[1], r[2], r[3]);
    }
}

extern "C" void kernel_launch(void* const* d_in, const int* in_sizes, int n_in,
                              void* d_out, int out_size) {
    const float* x = (const float*)d_in[0];
    float* out = (float*)d_out;
    int rows = out_size / D_DIM;   // 16384
    topk_keep_kernel<<<rows, NT>>>(x, out);
}